// round 5
// baseline (speedup 1.0000x reference)
#include <cuda_runtime.h>
#include <math.h>

#define N_CELLS 131072
#define IN_D 64
#define HID_D 128
#define OUT_D 64
#define CDIM 192            // IN_D + HID_D
#define H3 384              // 3*HID_D
#define GIN 65              // OUT_D + 1
#define NF 8
#define FS (N_CELLS / NF)   // 16384
#define DC (FS / 4)         // 4096

#define CELLS 16
#define MT 128

// ------------------------- device scratch (no runtime alloc) ----------------
__device__ float g_out[(size_t)N_CELLS * OUT_D];   // out = a - g
__device__ float g_t[N_CELLS];                     // per-cell tension
__device__ float g_W1aT[CDIM * HID_D];
__device__ float g_W1gT[CDIM * HID_D];
__device__ float g_W2aT[HID_D * OUT_D];
__device__ float g_W2gT[HID_D * OUT_D];
__device__ float g_WihT[GIN * H3];
__device__ float g_WhhT[HID_D * H3];
__device__ float g_fsum[NF * HID_D];
__device__ float g_fm[NF * HID_D];
__device__ float g_go[HID_D];
__device__ float g_wsum[OUT_D];
__device__ float g_sumexp;
__device__ float g_tsum;
__device__ int   g_tmax;   // float bits; valid since t >= 0

// ------------------------- prep: transpose weights + zero accumulators ------
__global__ void prep_kernel(const float* __restrict__ W1a, const float* __restrict__ W1g,
                            const float* __restrict__ W2a, const float* __restrict__ W2g,
                            const float* __restrict__ Wih, const float* __restrict__ Whh) {
    int i = blockIdx.x * blockDim.x + threadIdx.x;
    int stride = gridDim.x * blockDim.x;
    for (int idx = i; idx < HID_D * CDIM; idx += stride) {
        int j = idx / CDIM, k = idx % CDIM;
        g_W1aT[k * HID_D + j] = W1a[idx];
        g_W1gT[k * HID_D + j] = W1g[idx];
    }
    for (int idx = i; idx < OUT_D * HID_D; idx += stride) {
        int j = idx / HID_D, k = idx % HID_D;
        g_W2aT[k * OUT_D + j] = W2a[idx];
        g_W2gT[k * OUT_D + j] = W2g[idx];
    }
    for (int idx = i; idx < H3 * GIN; idx += stride) {
        int j = idx / GIN, k = idx % GIN;
        g_WihT[k * H3 + j] = Wih[idx];
    }
    for (int idx = i; idx < H3 * HID_D; idx += stride) {
        int j = idx / HID_D, k = idx % HID_D;
        g_WhhT[k * H3 + j] = Whh[idx];
    }
    for (int idx = i; idx < NF * HID_D; idx += stride) g_fsum[idx] = 0.f;
    for (int idx = i; idx < OUT_D; idx += stride)      g_wsum[idx] = 0.f;
    if (i == 0) { g_sumexp = 0.f; g_tsum = 0.f; g_tmax = 0; }
}

// ------------------------- main fused per-cell kernel -----------------------
__global__ void __launch_bounds__(MT) main_kernel(
    const float* __restrict__ x, const float* __restrict__ hiddens,
    const float* __restrict__ b1a, const float* __restrict__ b1g,
    const float* __restrict__ b2a, const float* __restrict__ b2g,
    const float* __restrict__ bih, const float* __restrict__ bhh,
    float* __restrict__ newh_out)
{
    __shared__ __align__(16) float sh_cT[CDIM][CELLS];        // 12 KB  (x|h, cell-minor)
    __shared__ __align__(16) float sh_hidT[2 * HID_D][CELLS]; // 16 KB  (relu hidden, a then g)
    __shared__ __align__(16) float sh_pT[2][OUT_D][CELLS];    // 8 KB   (layer2 partials)
    __shared__ __align__(16) float sh_outT[OUT_D][CELLS];     // 4 KB
    __shared__ __align__(16) float sh_t[CELLS];

    const int tid = threadIdx.x;
    const int n0 = blockIdx.x * CELLS;

    // ---- load x (broadcast rows 0..63) and h (rows 64..191) ----
    if (tid < IN_D) {
        float xv = x[tid];
        #pragma unroll
        for (int b = 0; b < CELLS; b++) sh_cT[tid][b] = xv;
    }
    for (int idx = tid; idx < CELLS * HID_D; idx += MT) {
        int b = idx >> 7, k = idx & 127;
        sh_cT[IN_D + k][b] = hiddens[(n0 + b) * HID_D + k];
    }
    __syncthreads();

    // ---- phase 1: hidden1 = relu(c @ W1{a,g}^T + b1{a,g}), thread = column ----
    {
        const int j = tid;
        float acca[CELLS], accg[CELLS];
        #pragma unroll
        for (int b = 0; b < CELLS; b++) { acca[b] = 0.f; accg[b] = 0.f; }
        #pragma unroll 4
        for (int k = 0; k < CDIM; k++) {
            float wa = g_W1aT[k * HID_D + j];
            float wg = g_W1gT[k * HID_D + j];
            #pragma unroll
            for (int b = 0; b < CELLS; b += 2) {
                float2 v = *(const float2*)&sh_cT[k][b];
                acca[b]     = fmaf(wa, v.x, acca[b]);
                acca[b + 1] = fmaf(wa, v.y, acca[b + 1]);
                accg[b]     = fmaf(wg, v.x, accg[b]);
                accg[b + 1] = fmaf(wg, v.y, accg[b + 1]);
            }
        }
        float ba = b1a[j], bg = b1g[j];
        #pragma unroll
        for (int b = 0; b < CELLS; b++) {
            sh_hidT[j][b]         = fmaxf(acca[b] + ba, 0.f);
            sh_hidT[HID_D + j][b] = fmaxf(accg[b] + bg, 0.f);
        }
    }
    __syncthreads();

    // ---- phase 2: layer2 (a and g halves in parallel across warps) ----
    {
        const int o = tid & 63, part = tid >> 6;
        const float* W2T = part ? g_W2gT : g_W2aT;
        const float (*hid)[CELLS] = &sh_hidT[part * HID_D];
        float acc[CELLS];
        #pragma unroll
        for (int b = 0; b < CELLS; b++) acc[b] = 0.f;
        #pragma unroll 4
        for (int j = 0; j < HID_D; j++) {
            float w = W2T[j * OUT_D + o];
            #pragma unroll
            for (int b = 0; b < CELLS; b += 2) {
                float2 v = *(const float2*)&hid[j][b];
                acc[b]     = fmaf(w, v.x, acc[b]);
                acc[b + 1] = fmaf(w, v.y, acc[b + 1]);
            }
        }
        #pragma unroll
        for (int b = 0; b < CELLS; b++) sh_pT[part][o][b] = acc[b];
    }
    __syncthreads();

    // ---- phase 2b: out = a - g (store to smem + gmem), t = mean(out^2) ----
    for (int idx = tid; idx < CELLS * OUT_D; idx += MT) {
        int b = idx >> 6, o = idx & 63;
        float v = sh_pT[0][o][b] - sh_pT[1][o][b] + b2a[o] - b2g[o];
        sh_outT[o][b] = v;
        g_out[(size_t)(n0 + b) * OUT_D + o] = v;
    }
    __syncthreads();
    if (tid < CELLS) {
        int b = tid;
        float s = 0.f;
        #pragma unroll
        for (int o = 0; o < OUT_D; o++) { float v = sh_outT[o][b]; s = fmaf(v, v, s); }
        float tv = s * (1.0f / OUT_D);
        sh_t[b] = tv;
        g_t[n0 + b] = tv;
        float mx = tv, sm = tv;
        #pragma unroll
        for (int off = 8; off > 0; off >>= 1) {
            mx = fmaxf(mx, __shfl_down_sync(0xffffu, mx, off));
            sm += __shfl_down_sync(0xffffu, sm, off);
        }
        if (b == 0) {
            atomicMax(&g_tmax, __float_as_int(mx));
            atomicAdd(&g_tsum, sm);
        }
    }
    __syncthreads();

    // ---- phase 3: GRU, thread = hidden dim d (owns gate cols d, d+128, d+256) ----
    {
        const int d = tid;
        const float bir = bih[d], biz = bih[HID_D + d], bin = bih[2 * HID_D + d];
        const float bhr = bhh[d], bhz = bhh[HID_D + d], bhn = bhh[2 * HID_D + d];
        float fsum_local = 0.f;
        #pragma unroll
        for (int chunk = 0; chunk < 2; chunk++) {
            const int bb = chunk * 8;
            float ir[8], iz[8], in_[8], hr[8], hz[8], hn[8];
            #pragma unroll
            for (int b = 0; b < 8; b++) {
                ir[b] = bir; iz[b] = biz; in_[b] = bin;
                hr[b] = bhr; hz[b] = bhz; hn[b] = bhn;
            }
            #pragma unroll 4
            for (int k = 0; k < OUT_D; k++) {
                float wr = g_WihT[k * H3 + d];
                float wz = g_WihT[k * H3 + HID_D + d];
                float wn = g_WihT[k * H3 + 2 * HID_D + d];
                #pragma unroll
                for (int b = 0; b < 8; b += 2) {
                    float2 v = *(const float2*)&sh_outT[k][bb + b];
                    ir[b] = fmaf(wr, v.x, ir[b]);  ir[b+1] = fmaf(wr, v.y, ir[b+1]);
                    iz[b] = fmaf(wz, v.x, iz[b]);  iz[b+1] = fmaf(wz, v.y, iz[b+1]);
                    in_[b] = fmaf(wn, v.x, in_[b]); in_[b+1] = fmaf(wn, v.y, in_[b+1]);
                }
            }
            {   // gru input column 64 = tension
                float wr = g_WihT[OUT_D * H3 + d];
                float wz = g_WihT[OUT_D * H3 + HID_D + d];
                float wn = g_WihT[OUT_D * H3 + 2 * HID_D + d];
                #pragma unroll
                for (int b = 0; b < 8; b++) {
                    float v = sh_t[bb + b];
                    ir[b] = fmaf(wr, v, ir[b]);
                    iz[b] = fmaf(wz, v, iz[b]);
                    in_[b] = fmaf(wn, v, in_[b]);
                }
            }
            #pragma unroll 4
            for (int k = 0; k < HID_D; k++) {
                float wr = g_WhhT[k * H3 + d];
                float wz = g_WhhT[k * H3 + HID_D + d];
                float wn = g_WhhT[k * H3 + 2 * HID_D + d];
                #pragma unroll
                for (int b = 0; b < 8; b += 2) {
                    float2 v = *(const float2*)&sh_cT[IN_D + k][bb + b];
                    hr[b] = fmaf(wr, v.x, hr[b]);  hr[b+1] = fmaf(wr, v.y, hr[b+1]);
                    hz[b] = fmaf(wz, v.x, hz[b]);  hz[b+1] = fmaf(wz, v.y, hz[b+1]);
                    hn[b] = fmaf(wn, v.x, hn[b]);  hn[b+1] = fmaf(wn, v.y, hn[b+1]);
                }
            }
            #pragma unroll
            for (int b = 0; b < 8; b++) {
                float r = 1.f / (1.f + expf(-(ir[b] + hr[b])));
                float z = 1.f / (1.f + expf(-(iz[b] + hz[b])));
                float nn = tanhf(in_[b] + r * hn[b]);
                float h = sh_cT[IN_D + d][bb + b];
                float nh = (1.f - z) * nn + z * h;
                fsum_local += nh;
                newh_out[(n0 + bb + b) * HID_D + d] = nh;
            }
        }
        int f = n0 / FS;   // all 16 cells in the CTA share one faction (FS % CELLS == 0)
        atomicAdd(&g_fsum[f * HID_D + d], fsum_local);
    }
}

// ------------------------- faction means / global opinion / t.mean ----------
__global__ void faction_kernel() {
    int d = threadIdx.x;  // 128
    float s = 0.f;
    for (int f = 0; f < NF; f++) {
        float fm = g_fsum[f * HID_D + d] * (1.0f / FS);
        g_fm[f * HID_D + d] = fm;
        s += fm;
    }
    g_go[d] = s * (1.0f / NF);
}

// ------------------------- softmax numerator/denominator + w @ out ----------
#define K3_CELLS 512
__global__ void __launch_bounds__(256) softmax_kernel() {
    __shared__ float sh_e[K3_CELLS];
    __shared__ float sh_es;
    int tid = threadIdx.x;
    int base = blockIdx.x * K3_CELLS;
    if (tid == 0) sh_es = 0.f;
    __syncthreads();
    float tmax = __int_as_float(g_tmax);
    float es = 0.f;
    for (int c = tid; c < K3_CELLS; c += 256) {
        float e = expf(g_t[base + c] - tmax);
        sh_e[c] = e;
        es += e;
    }
    #pragma unroll
    for (int off = 16; off > 0; off >>= 1) es += __shfl_down_sync(0xffffffffu, es, off);
    if ((tid & 31) == 0) atomicAdd(&sh_es, es);
    __syncthreads();
    if (tid == 0) atomicAdd(&g_sumexp, sh_es);
    int o = tid & 63, grp = tid >> 6;
    float acc = 0.f;
    for (int c = grp; c < K3_CELLS; c += 4)
        acc = fmaf(sh_e[c], g_out[(size_t)(base + c) * OUT_D + o], acc);
    atomicAdd(&g_wsum[o], acc);
}

// ------------------------- output head + t.mean ------------------------------
__global__ void head_kernel(const float* __restrict__ Wo, const float* __restrict__ bo,
                            float* __restrict__ out) {
    int i = threadIdx.x;  // 64
    float inv = 1.f / g_sumexp;
    float acc = bo[i];
    #pragma unroll 4
    for (int j = 0; j < OUT_D; j++)
        acc = fmaf(g_wsum[j] * inv, Wo[i * OUT_D + j], acc);
    out[i] = acc;
    if (i == 0) out[OUT_D] = g_tsum * (1.0f / N_CELLS);
}

// ------------------------- faction sync finalize (in place) ------------------
__global__ void __launch_bounds__(256) finalize_kernel(float* __restrict__ newh,
                                                       const int* __restrict__ step) {
    int idx = blockIdx.x * blockDim.x + threadIdx.x;  // < N_CELLS * HID_D
    int n = idx >> 7, d = idx & 127;
    float pre = newh[idx];
    int f = n >> 14;  // FS == 16384
    float v = 0.85f * pre + 0.15f * g_fm[f * HID_D + d];
    if (*step > 5 && (n & (FS - 1)) < DC)
        v = 0.85f * v + 0.15f * g_go[d];
    newh[idx] = v;
}

// ------------------------- launch ---------------------------------------------
extern "C" void kernel_launch(void* const* d_in, const int* in_sizes, int n_in,
                              void* d_out, int out_size) {
    const float* x       = (const float*)d_in[0];
    const float* hiddens = (const float*)d_in[1];
    const float* W1a = (const float*)d_in[2];  const float* b1a = (const float*)d_in[3];
    const float* W2a = (const float*)d_in[4];  const float* b2a = (const float*)d_in[5];
    const float* W1g = (const float*)d_in[6];  const float* b1g = (const float*)d_in[7];
    const float* W2g = (const float*)d_in[8];  const float* b2g = (const float*)d_in[9];
    const float* Wih = (const float*)d_in[10]; const float* Whh = (const float*)d_in[11];
    const float* bih = (const float*)d_in[12]; const float* bhh = (const float*)d_in[13];
    const float* Wo  = (const float*)d_in[14]; const float* bo  = (const float*)d_in[15];
    const int*   step = (const int*)d_in[16];

    float* out = (float*)d_out;
    float* newh = out + OUT_D + 1;  // [pred(64) | t.mean(1) | new_h(131072*128)]

    prep_kernel<<<64, 256>>>(W1a, W1g, W2a, W2g, Wih, Whh);
    main_kernel<<<N_CELLS / CELLS, MT>>>(x, hiddens, b1a, b1g, b2a, b2g, bih, bhh, newh);
    faction_kernel<<<1, HID_D>>>();
    softmax_kernel<<<N_CELLS / K3_CELLS, 256>>>();
    head_kernel<<<1, OUT_D>>>(Wo, bo, out);
    finalize_kernel<<<(N_CELLS * HID_D) / 256, 256>>>(newh, step);
}

// round 11
// speedup vs baseline: 1.1245x; 1.1245x over previous
#include <cuda_runtime.h>
#include <math.h>

typedef unsigned long long ull;

#define N_CELLS 131072
#define IN_D 64
#define HID_D 128
#define OUT_D 64
#define CDIM 192            // IN_D + HID_D
#define H3 384              // 3*HID_D
#define GIN 65              // OUT_D + 1
#define NF 8
#define FS (N_CELLS / NF)   // 16384
#define DC (FS / 4)         // 4096

#define CELLS 16
#define MT 128

// ---------------- packed f32x2 helpers (Blackwell FFMA2) --------------------
__device__ __forceinline__ ull ffma2(ull a, ull b, ull c) {
    ull d;
    asm("fma.rn.f32x2 %0, %1, %2, %3;" : "=l"(d) : "l"(a), "l"(b), "l"(c));
    return d;
}
__device__ __forceinline__ ull pack2(float v) {
    ull d;
    asm("mov.b64 %0, {%1, %1};" : "=l"(d) : "f"(v));
    return d;
}
__device__ __forceinline__ float2 unpk(ull u) {
    float lo, hi;
    asm("mov.b64 {%0, %1}, %2;" : "=f"(lo), "=f"(hi) : "l"(u));
    return make_float2(lo, hi);
}

// ------------------------- device scratch (no runtime alloc) ----------------
__device__ float  g_out[(size_t)N_CELLS * OUT_D];   // out = a - g
__device__ float  g_t[N_CELLS];                     // per-cell tension
__device__ float2 g_W1I[CDIM * HID_D];              // (wa, wg) at k*128+j
__device__ float  g_W2aT[HID_D * OUT_D];            // j*64+o
__device__ float  g_W2gT[HID_D * OUT_D];
__device__ float  g_WihT3[GIN * 3 * HID_D];         // (k*3+gate)*128+d
__device__ float  g_WhhT3[HID_D * 3 * HID_D];
__device__ float  g_fsum[NF * HID_D];
__device__ float  g_fm[NF * HID_D];
__device__ float  g_go[HID_D];
__device__ float  g_wsum[OUT_D];
__device__ float  g_sumexp;
__device__ float  g_tsum;
__device__ int    g_tmax;   // float bits; valid since t >= 0

// ------------------------- prep: transpose weights + zero accumulators ------
__global__ void prep_kernel(const float* __restrict__ W1a, const float* __restrict__ W1g,
                            const float* __restrict__ W2a, const float* __restrict__ W2g,
                            const float* __restrict__ Wih, const float* __restrict__ Whh) {
    int i = blockIdx.x * blockDim.x + threadIdx.x;
    int stride = gridDim.x * blockDim.x;
    for (int idx = i; idx < CDIM * HID_D; idx += stride) {
        int k = idx >> 7, j = idx & 127;
        g_W1I[idx] = make_float2(W1a[j * CDIM + k], W1g[j * CDIM + k]);
    }
    for (int idx = i; idx < HID_D * OUT_D; idx += stride) {
        int j = idx >> 6, o = idx & 63;
        g_W2aT[idx] = W2a[o * HID_D + j];
        g_W2gT[idx] = W2g[o * HID_D + j];
    }
    for (int idx = i; idx < GIN * 3 * HID_D; idx += stride) {
        int k = idx / H3, r = idx % H3, gate = r >> 7, d = r & 127;
        g_WihT3[idx] = Wih[(gate * HID_D + d) * GIN + k];
    }
    for (int idx = i; idx < HID_D * 3 * HID_D; idx += stride) {
        int k = idx / H3, r = idx % H3, gate = r >> 7, d = r & 127;
        g_WhhT3[idx] = Whh[(gate * HID_D + d) * HID_D + k];
    }
    for (int idx = i; idx < NF * HID_D; idx += stride) g_fsum[idx] = 0.f;
    for (int idx = i; idx < OUT_D; idx += stride)      g_wsum[idx] = 0.f;
    if (i == 0) { g_sumexp = 0.f; g_tsum = 0.f; g_tmax = 0; }
}

// ------------------------- main fused per-cell kernel -----------------------
__global__ void __launch_bounds__(MT, 3) main_kernel(
    const float* __restrict__ x, const float* __restrict__ hiddens,
    const float* __restrict__ b1a, const float* __restrict__ b1g,
    const float* __restrict__ b2a, const float* __restrict__ b2g,
    const float* __restrict__ bih, const float* __restrict__ bhh,
    float* __restrict__ newh_out)
{
    __shared__ __align__(16) float sh_cT[CDIM][CELLS];         // 12 KB (x|h, cell-minor)
    __shared__ __align__(16) float sh_hidT[2 * HID_D][CELLS];  // 16 KB (relu hidden a,g)
    __shared__ __align__(16) float sh_pT[2][CELLS][OUT_D];     // 8 KB  (layer2, cell-major)
    __shared__ __align__(16) float sh_outT[GIN][CELLS];        // 4.1 KB (row 64 = tension)

    const int tid = threadIdx.x;
    const int n0 = blockIdx.x * CELLS;
    float hreg[CELLS];   // this thread's own hidden row d=tid across all cells

    // ---- load x (broadcast rows 0..63) and h (rows 64..191) ----
    if (tid < IN_D) {
        float xv = x[tid];
        #pragma unroll
        for (int b = 0; b < CELLS; b++) sh_cT[tid][b] = xv;
    }
    {
        const float* hp = hiddens + (size_t)n0 * HID_D + tid;
        #pragma unroll
        for (int m = 0; m < CELLS; m++) {
            float hv = hp[(size_t)m * HID_D];
            hreg[m] = hv;
            sh_cT[IN_D + tid][m] = hv;
        }
    }
    __syncthreads();

    // ---- phase 1: hidden1 = relu(c @ W1{a,g}^T + b1{a,g}), thread = column ----
    {
        const int j = tid;
        ull a2[8], g2[8];
        #pragma unroll
        for (int q = 0; q < 8; q++) { a2[q] = 0ull; g2[q] = 0ull; }
        #pragma unroll 2
        for (int k = 0; k < CDIM; k++) {
            float2 w = g_W1I[k * HID_D + j];
            ull wa2 = pack2(w.x), wg2 = pack2(w.y);
            #pragma unroll
            for (int q = 0; q < 4; q++) {
                ulonglong2 v = *(const ulonglong2*)&sh_cT[k][q * 4];
                a2[2 * q]     = ffma2(wa2, v.x, a2[2 * q]);
                a2[2 * q + 1] = ffma2(wa2, v.y, a2[2 * q + 1]);
                g2[2 * q]     = ffma2(wg2, v.x, g2[2 * q]);
                g2[2 * q + 1] = ffma2(wg2, v.y, g2[2 * q + 1]);
            }
        }
        float ba = b1a[j], bg = b1g[j];
        #pragma unroll
        for (int q = 0; q < 8; q++) {
            float2 av = unpk(a2[q]), gv = unpk(g2[q]);
            sh_hidT[j][2 * q]             = fmaxf(av.x + ba, 0.f);
            sh_hidT[j][2 * q + 1]         = fmaxf(av.y + ba, 0.f);
            sh_hidT[HID_D + j][2 * q]     = fmaxf(gv.x + bg, 0.f);
            sh_hidT[HID_D + j][2 * q + 1] = fmaxf(gv.y + bg, 0.f);
        }
    }
    __syncthreads();

    // ---- phase 2: layer2 (a and g halves in parallel across warp-halves) ----
    {
        const int o = tid & 63, part = tid >> 6;
        const float* W2T = part ? g_W2gT : g_W2aT;
        const float (*hid)[CELLS] = &sh_hidT[part * HID_D];
        ull acc[8];
        #pragma unroll
        for (int q = 0; q < 8; q++) acc[q] = 0ull;
        #pragma unroll 2
        for (int jj = 0; jj < HID_D; jj++) {
            ull w2 = pack2(W2T[jj * OUT_D + o]);
            #pragma unroll
            for (int q = 0; q < 4; q++) {
                ulonglong2 v = *(const ulonglong2*)&hid[jj][q * 4];
                acc[2 * q]     = ffma2(w2, v.x, acc[2 * q]);
                acc[2 * q + 1] = ffma2(w2, v.y, acc[2 * q + 1]);
            }
        }
        float bb = part ? b2g[o] : b2a[o];
        #pragma unroll
        for (int q = 0; q < 8; q++) {
            float2 p = unpk(acc[q]);
            sh_pT[part][2 * q][o]     = p.x + bb;
            sh_pT[part][2 * q + 1][o] = p.y + bb;
        }
    }
    __syncthreads();

    // ---- phase 2b: out = a - g (smem + gmem), t = mean(out^2) ----
    #pragma unroll
    for (int idx = tid; idx < CELLS * OUT_D; idx += MT) {
        int b = idx >> 6, o = idx & 63;
        float v = sh_pT[0][b][o] - sh_pT[1][b][o];
        sh_outT[o][b] = v;
        g_out[(size_t)(n0 + b) * OUT_D + o] = v;
    }
    __syncthreads();
    if (tid < CELLS) {
        int b = tid;
        float s = 0.f;
        #pragma unroll
        for (int o = 0; o < OUT_D; o++) { float v = sh_outT[o][b]; s = fmaf(v, v, s); }
        float tv = s * (1.0f / OUT_D);
        sh_outT[GIN - 1][b] = tv;       // tension as row 64 for uniform GRU loop
        g_t[n0 + b] = tv;
        float mx = tv, sm = tv;
        #pragma unroll
        for (int off = 8; off > 0; off >>= 1) {
            mx = fmaxf(mx, __shfl_down_sync(0xffffu, mx, off));
            sm += __shfl_down_sync(0xffffu, sm, off);
        }
        if (b == 0) {
            atomicMax(&g_tmax, __float_as_int(mx));
            atomicAdd(&g_tsum, sm);
        }
    }
    __syncthreads();

    // ---- phase 3: GRU, thread = hidden dim d, ALL 16 cells in one pass ----
    {
        const int d = tid;
        // r,z accumulate (gi+gh) combined; n keeps i_n and h_n separate.
        ull r2[8], z2[8], n2[8], hn2[8];
        {
            ull br = pack2(bih[d] + bhh[d]);
            ull bz = pack2(bih[HID_D + d] + bhh[HID_D + d]);
            ull bn = pack2(bih[2 * HID_D + d]);
            ull bh = pack2(bhh[2 * HID_D + d]);
            #pragma unroll
            for (int q = 0; q < 8; q++) { r2[q] = br; z2[q] = bz; n2[q] = bn; hn2[q] = bh; }
        }
        const float* Wi = g_WihT3 + d;
        #pragma unroll 2
        for (int k = 0; k < GIN; k++) {
            ull wr2 = pack2(Wi[(k * 3 + 0) * HID_D]);
            ull wz2 = pack2(Wi[(k * 3 + 1) * HID_D]);
            ull wn2 = pack2(Wi[(k * 3 + 2) * HID_D]);
            #pragma unroll
            for (int q = 0; q < 4; q++) {
                ulonglong2 v = *(const ulonglong2*)&sh_outT[k][q * 4];
                r2[2 * q]     = ffma2(wr2, v.x, r2[2 * q]);
                r2[2 * q + 1] = ffma2(wr2, v.y, r2[2 * q + 1]);
                z2[2 * q]     = ffma2(wz2, v.x, z2[2 * q]);
                z2[2 * q + 1] = ffma2(wz2, v.y, z2[2 * q + 1]);
                n2[2 * q]     = ffma2(wn2, v.x, n2[2 * q]);
                n2[2 * q + 1] = ffma2(wn2, v.y, n2[2 * q + 1]);
            }
        }
        const float* Wh = g_WhhT3 + d;
        #pragma unroll 2
        for (int k = 0; k < HID_D; k++) {
            ull wr2 = pack2(Wh[(k * 3 + 0) * HID_D]);
            ull wz2 = pack2(Wh[(k * 3 + 1) * HID_D]);
            ull wn2 = pack2(Wh[(k * 3 + 2) * HID_D]);
            #pragma unroll
            for (int q = 0; q < 4; q++) {
                ulonglong2 v = *(const ulonglong2*)&sh_cT[IN_D + k][q * 4];
                r2[2 * q]      = ffma2(wr2, v.x, r2[2 * q]);
                r2[2 * q + 1]  = ffma2(wr2, v.y, r2[2 * q + 1]);
                z2[2 * q]      = ffma2(wz2, v.x, z2[2 * q]);
                z2[2 * q + 1]  = ffma2(wz2, v.y, z2[2 * q + 1]);
                hn2[2 * q]     = ffma2(wn2, v.x, hn2[2 * q]);
                hn2[2 * q + 1] = ffma2(wn2, v.y, hn2[2 * q + 1]);
            }
        }
        float fsum_local = 0.f;
        #pragma unroll
        for (int q = 0; q < 8; q++) {
            float2 rf = unpk(r2[q]), zf = unpk(z2[q]);
            float2 inn = unpk(n2[q]), hnf = unpk(hn2[q]);
            {
                float r = 1.f / (1.f + expf(-rf.x));
                float z = 1.f / (1.f + expf(-zf.x));
                float nn = tanhf(inn.x + r * hnf.x);
                float nh = (1.f - z) * nn + z * hreg[2 * q];
                fsum_local += nh;
                newh_out[(size_t)(n0 + 2 * q) * HID_D + d] = nh;
            }
            {
                float r = 1.f / (1.f + expf(-rf.y));
                float z = 1.f / (1.f + expf(-zf.y));
                float nn = tanhf(inn.y + r * hnf.y);
                float nh = (1.f - z) * nn + z * hreg[2 * q + 1];
                fsum_local += nh;
                newh_out[(size_t)(n0 + 2 * q + 1) * HID_D + d] = nh;
            }
        }
        int f = n0 / FS;   // all 16 cells share one faction (FS % CELLS == 0)
        atomicAdd(&g_fsum[f * HID_D + d], fsum_local);
    }
}

// ------------------------- faction means / global opinion -------------------
__global__ void faction_kernel() {
    int d = threadIdx.x;  // 128
    float s = 0.f;
    for (int f = 0; f < NF; f++) {
        float fm = g_fsum[f * HID_D + d] * (1.0f / FS);
        g_fm[f * HID_D + d] = fm;
        s += fm;
    }
    g_go[d] = s * (1.0f / NF);
}

// ------------------------- softmax numerator/denominator + w @ out ----------
#define K3_CELLS 256
__global__ void __launch_bounds__(256) softmax_kernel() {
    __shared__ float sh_e[K3_CELLS];
    __shared__ float sh_w[256];
    __shared__ float sh_es;
    int tid = threadIdx.x;
    int base = blockIdx.x * K3_CELLS;
    if (tid == 0) sh_es = 0.f;
    __syncthreads();
    float tmax = __int_as_float(g_tmax);
    float e = expf(g_t[base + tid] - tmax);
    sh_e[tid] = e;
    float es = e;
    #pragma unroll
    for (int off = 16; off > 0; off >>= 1) es += __shfl_down_sync(0xffffffffu, es, off);
    if ((tid & 31) == 0) atomicAdd(&sh_es, es);
    __syncthreads();
    if (tid == 0) atomicAdd(&g_sumexp, sh_es);
    int o = tid & 63, grp = tid >> 6;
    float acc = 0.f;
    for (int c = grp; c < K3_CELLS; c += 4)
        acc = fmaf(sh_e[c], g_out[(size_t)(base + c) * OUT_D + o], acc);
    sh_w[tid] = acc;
    __syncthreads();
    if (tid < OUT_D)
        atomicAdd(&g_wsum[tid], sh_w[tid] + sh_w[64 + tid] + sh_w[128 + tid] + sh_w[192 + tid]);
}

// ------------------------- output head + t.mean ------------------------------
__global__ void head_kernel(const float* __restrict__ Wo, const float* __restrict__ bo,
                            float* __restrict__ out) {
    int i = threadIdx.x;  // 64
    float inv = 1.f / g_sumexp;
    float acc = bo[i];
    #pragma unroll 4
    for (int j = 0; j < OUT_D; j++)
        acc = fmaf(g_wsum[j] * inv, Wo[i * OUT_D + j], acc);
    out[i] = acc;
    if (i == 0) out[OUT_D] = g_tsum * (1.0f / N_CELLS);
}

// ------------------------- faction sync finalize (in place) ------------------
__global__ void __launch_bounds__(256) finalize_kernel(float* __restrict__ newh,
                                                       const int* __restrict__ step) {
    int idx = blockIdx.x * blockDim.x + threadIdx.x;  // < N_CELLS * HID_D
    int n = idx >> 7, d = idx & 127;
    float pre = newh[idx];
    int f = n >> 14;  // FS == 16384
    float v = 0.85f * pre + 0.15f * g_fm[f * HID_D + d];
    if (*step > 5 && (n & (FS - 1)) < DC)
        v = 0.85f * v + 0.15f * g_go[d];
    newh[idx] = v;
}

// ------------------------- launch ---------------------------------------------
extern "C" void kernel_launch(void* const* d_in, const int* in_sizes, int n_in,
                              void* d_out, int out_size) {
    const float* x       = (const float*)d_in[0];
    const float* hiddens = (const float*)d_in[1];
    const float* W1a = (const float*)d_in[2];  const float* b1a = (const float*)d_in[3];
    const float* W2a = (const float*)d_in[4];  const float* b2a = (const float*)d_in[5];
    const float* W1g = (const float*)d_in[6];  const float* b1g = (const float*)d_in[7];
    const float* W2g = (const float*)d_in[8];  const float* b2g = (const float*)d_in[9];
    const float* Wih = (const float*)d_in[10]; const float* Whh = (const float*)d_in[11];
    const float* bih = (const float*)d_in[12]; const float* bhh = (const float*)d_in[13];
    const float* Wo  = (const float*)d_in[14]; const float* bo  = (const float*)d_in[15];
    const int*   step = (const int*)d_in[16];

    float* out = (float*)d_out;
    float* newh = out + OUT_D + 1;  // [pred(64) | t.mean(1) | new_h(131072*128)]

    prep_kernel<<<128, 256>>>(W1a, W1g, W2a, W2g, Wih, Whh);
    main_kernel<<<N_CELLS / CELLS, MT>>>(x, hiddens, b1a, b1g, b2a, b2g, bih, bhh, newh);
    faction_kernel<<<1, HID_D>>>();
    softmax_kernel<<<N_CELLS / K3_CELLS, 256>>>();
    head_kernel<<<1, OUT_D>>>(Wo, bo, out);
    finalize_kernel<<<(N_CELLS * HID_D) / 256, 256>>>(newh, step);
}

// round 15
// speedup vs baseline: 1.4179x; 1.2609x over previous
#include <cuda_runtime.h>
#include <math.h>

typedef unsigned long long ull;

#define N_CELLS 131072
#define IN_D 64
#define HID_D 128
#define OUT_D 64
#define H3 384
#define GIN 65              // OUT_D + 1
#define NF 8
#define FS (N_CELLS / NF)   // 16384
#define DC (FS / 4)         // 4096

#define CELLS 32
#define HALF 16
#define MT 256
#define NCTAS (N_CELLS / CELLS)   // 4096
#define SH 36               // padded cell-minor row stride (floats): 144B, 16B-aligned, bank shift 4

// ---------------- packed f32x2 helpers (Blackwell FFMA2) --------------------
__device__ __forceinline__ ull ffma2(ull a, ull b, ull c) {
    ull d;
    asm("fma.rn.f32x2 %0, %1, %2, %3;" : "=l"(d) : "l"(a), "l"(b), "l"(c));
    return d;
}
__device__ __forceinline__ ull pack2(float v) {
    ull d;
    asm("mov.b64 %0, {%1, %1};" : "=l"(d) : "f"(v));
    return d;
}
__device__ __forceinline__ float2 unpk(ull u) {
    float lo, hi;
    asm("mov.b64 {%0, %1}, %2;" : "=f"(lo), "=f"(hi) : "l"(u));
    return make_float2(lo, hi);
}

// ------------------------- device scratch (no runtime alloc) ----------------
__device__ float2 g_W1I[HID_D * HID_D];      // (wa,wg) for h-part only, k*128+j
__device__ float  g_hb1a[HID_D];             // b1a + W1a_x @ x   (x folded)
__device__ float  g_hb1g[HID_D];
__device__ float  g_W2aT[HID_D * OUT_D];     // j*64+o
__device__ float  g_W2gT[HID_D * OUT_D];
__device__ float  g_b2d[OUT_D];              // b2a - b2g
__device__ float2 g_WiRZ[GIN * HID_D];       // (wr,wz) at k*128+d
__device__ float  g_WiN[GIN * HID_D];
__device__ float2 g_WhRZ[HID_D * HID_D];
__device__ float  g_WhN[HID_D * HID_D];
__device__ float  g_gb[4 * HID_D];           // [r: bih+bhh][z: bih+bhh][i_n bias][h_n bias]
__device__ float  g_fsum[NF * HID_D];
__device__ float  g_fm[NF * HID_D];
__device__ float  g_go[HID_D];
__device__ float  g_wsum[OUT_D];
__device__ float  g_sumexp;
__device__ float  g_tsum;

// ------------------------- prep: fold/transpose weights ---------------------
__global__ void prep_kernel(const float* __restrict__ x,
                            const float* __restrict__ W1a, const float* __restrict__ b1a,
                            const float* __restrict__ W1g, const float* __restrict__ b1g,
                            const float* __restrict__ W2a, const float* __restrict__ b2a,
                            const float* __restrict__ W2g, const float* __restrict__ b2g,
                            const float* __restrict__ Wih, const float* __restrict__ Whh,
                            const float* __restrict__ bih, const float* __restrict__ bhh) {
    int i = blockIdx.x * blockDim.x + threadIdx.x;
    int stride = gridDim.x * blockDim.x;
    const int CD = IN_D + HID_D;  // 192
    // layer1 h-part transposed + interleaved
    for (int idx = i; idx < HID_D * HID_D; idx += stride) {
        int k = idx >> 7, j = idx & 127;
        g_W1I[idx] = make_float2(W1a[j * CD + IN_D + k], W1g[j * CD + IN_D + k]);
    }
    // fold x into layer1 bias
    for (int idx = i; idx < 2 * HID_D; idx += stride) {
        int j = idx & 127, eng = idx >> 7;
        const float* W = eng ? W1g : W1a;
        float acc = eng ? b1g[j] : b1a[j];
        for (int k = 0; k < IN_D; k++) acc = fmaf(W[j * CD + k], x[k], acc);
        if (eng) g_hb1g[j] = acc; else g_hb1a[j] = acc;
    }
    for (int idx = i; idx < HID_D * OUT_D; idx += stride) {
        int j = idx >> 6, o = idx & 63;
        g_W2aT[idx] = W2a[o * HID_D + j];
        g_W2gT[idx] = W2g[o * HID_D + j];
    }
    for (int idx = i; idx < OUT_D; idx += stride) {
        g_b2d[idx] = b2a[idx] - b2g[idx];
        g_wsum[idx] = 0.f;
    }
    for (int idx = i; idx < GIN * HID_D; idx += stride) {
        int k = idx >> 7, d = idx & 127;
        g_WiRZ[idx] = make_float2(Wih[d * GIN + k], Wih[(HID_D + d) * GIN + k]);
        g_WiN[idx]  = Wih[(2 * HID_D + d) * GIN + k];
    }
    for (int idx = i; idx < HID_D * HID_D; idx += stride) {
        int k = idx >> 7, d = idx & 127;
        g_WhRZ[idx] = make_float2(Whh[d * HID_D + k], Whh[(HID_D + d) * HID_D + k]);
        g_WhN[idx]  = Whh[(2 * HID_D + d) * HID_D + k];
    }
    for (int idx = i; idx < HID_D; idx += stride) {
        g_gb[idx]             = bih[idx] + bhh[idx];
        g_gb[HID_D + idx]     = bih[HID_D + idx] + bhh[HID_D + idx];
        g_gb[2 * HID_D + idx] = bih[2 * HID_D + idx];
        g_gb[3 * HID_D + idx] = bhh[2 * HID_D + idx];
    }
    for (int idx = i; idx < NF * HID_D; idx += stride) g_fsum[idx] = 0.f;
    if (i == 0) { g_sumexp = 0.f; g_tsum = 0.f; }
}

// ------------------------- dynamic smem layout (floats) ---------------------
#define OFF_H    0                         // sh_h   [128][SH]
#define OFF_HID  (OFF_H + HID_D * SH)      // sh_hid [256][SH]
#define OFF_P    (OFF_HID + 2 * HID_D * SH)// sh_p   [2][32][64]
#define OFF_OT   (OFF_P + 2 * CELLS * OUT_D)  // sh_oT [65][SH]
#define OFF_OC   (OFF_OT + GIN * SH)       // sh_oC  [32][64]
#define OFF_E    (OFF_OC + CELLS * OUT_D)  // sh_e   [32]
#define SMEM_FLOATS (OFF_E + CELLS)
#define SMEM_BYTES  (SMEM_FLOATS * 4)

// ------------------------- main fused per-cell kernel -----------------------
__global__ void __launch_bounds__(MT, 2) main_kernel(
    const float* __restrict__ hiddens, float* __restrict__ newh_out)
{
    extern __shared__ __align__(16) float smem[];
    float* sh_h   = smem + OFF_H;
    float* sh_hid = smem + OFF_HID;
    float* sh_p   = smem + OFF_P;
    float* sh_oT  = smem + OFF_OT;
    float* sh_oC  = smem + OFF_OC;
    float* sh_e   = smem + OFF_E;

    const int tid = threadIdx.x;
    const int n0 = blockIdx.x * CELLS;

    // ---- load h transposed (cell-minor, padded rows) ----
    #pragma unroll
    for (int it = 0; it < CELLS * HID_D / MT; it++) {
        int idx = tid + it * MT;
        int m = idx >> 7, d = idx & 127;
        sh_h[d * SH + m] = hiddens[(size_t)(n0 + m) * HID_D + d];
    }
    __syncthreads();

    const int lane128 = tid & 127, half = tid >> 7, cb = half * HALF;

    // ---- phase 1: hidden1 = relu(h @ W1h^T + folded bias) ----
    {
        const int j = lane128;
        ull a2[8], g2[8];
        #pragma unroll
        for (int q = 0; q < 8; q++) { a2[q] = 0ull; g2[q] = 0ull; }
        #pragma unroll 4
        for (int k = 0; k < HID_D; k++) {
            float2 w = g_W1I[k * HID_D + j];
            ull wa2 = pack2(w.x), wg2 = pack2(w.y);
            const float* vp = sh_h + k * SH + cb;
            #pragma unroll
            for (int q = 0; q < 4; q++) {
                ulonglong2 v = *(const ulonglong2*)(vp + q * 4);
                a2[2 * q]     = ffma2(wa2, v.x, a2[2 * q]);
                a2[2 * q + 1] = ffma2(wa2, v.y, a2[2 * q + 1]);
                g2[2 * q]     = ffma2(wg2, v.x, g2[2 * q]);
                g2[2 * q + 1] = ffma2(wg2, v.y, g2[2 * q + 1]);
            }
        }
        float ba = g_hb1a[j], bg = g_hb1g[j];
        float* pa = sh_hid + j * SH + cb;
        float* pg = sh_hid + (HID_D + j) * SH + cb;
        #pragma unroll
        for (int q = 0; q < 8; q++) {
            float2 av = unpk(a2[q]), gv = unpk(g2[q]);
            *(float2*)(pa + 2 * q) = make_float2(fmaxf(av.x + ba, 0.f), fmaxf(av.y + ba, 0.f));
            *(float2*)(pg + 2 * q) = make_float2(fmaxf(gv.x + bg, 0.f), fmaxf(gv.y + bg, 0.f));
        }
    }
    __syncthreads();

    // ---- phase 2: layer2 (a/g split across warp groups) ----
    {
        const int o = tid & 63, part = (tid >> 6) & 1;
        const float* W2T = part ? g_W2gT : g_W2aT;
        const float* hid = sh_hid + part * HID_D * SH + cb;
        ull acc[8];
        #pragma unroll
        for (int q = 0; q < 8; q++) acc[q] = 0ull;
        #pragma unroll 4
        for (int jj = 0; jj < HID_D; jj++) {
            ull w2 = pack2(W2T[jj * OUT_D + o]);
            const float* vp = hid + jj * SH;
            #pragma unroll
            for (int q = 0; q < 4; q++) {
                ulonglong2 v = *(const ulonglong2*)(vp + q * 4);
                acc[2 * q]     = ffma2(w2, v.x, acc[2 * q]);
                acc[2 * q + 1] = ffma2(w2, v.y, acc[2 * q + 1]);
            }
        }
        float* pp = sh_p + part * CELLS * OUT_D + cb * OUT_D + o;
        #pragma unroll
        for (int q = 0; q < 8; q++) {
            float2 p = unpk(acc[q]);
            pp[(2 * q) * OUT_D]     = p.x;
            pp[(2 * q + 1) * OUT_D] = p.y;
        }
    }
    __syncthreads();

    // ---- phase 2b: out = a - g + (b2a-b2g), dual-layout store ----
    #pragma unroll
    for (int it = 0; it < CELLS * OUT_D / MT; it++) {
        int idx = tid + it * MT;
        int b = idx >> 6, o = idx & 63;
        float v = sh_p[b * OUT_D + o] - sh_p[CELLS * OUT_D + b * OUT_D + o] + g_b2d[o];
        sh_oT[o * SH + b] = v;
        sh_oC[b * OUT_D + o] = v;
    }
    __syncthreads();

    // ---- tension + exp (no max subtraction: softmax is shift-invariant) ----
    if (tid < CELLS) {
        int b = tid;
        float s = 0.f;
        #pragma unroll
        for (int o = 0; o < OUT_D; o++) { float v = sh_oT[o * SH + b]; s = fmaf(v, v, s); }
        float tv = s * (1.0f / OUT_D);
        sh_oT[(GIN - 1) * SH + b] = tv;   // GRU input column 64
        float e = expf(tv);
        sh_e[b] = e;
        float es = e, ts = tv;
        #pragma unroll
        for (int off = 16; off > 0; off >>= 1) {
            es += __shfl_down_sync(0xffffffffu, es, off);
            ts += __shfl_down_sync(0xffffffffu, ts, off);
        }
        if (b == 0) {
            atomicAdd(&g_sumexp, es);
            atomicAdd(&g_tsum, ts);
        }
    }
    __syncthreads();

    // ---- softmax numerator partial: wsum_o += sum_b e_b * out[b][o] ----
    if (tid < OUT_D) {
        const int o = tid;
        float acc = 0.f;
        #pragma unroll 4
        for (int b = 0; b < CELLS; b++)
            acc = fmaf(sh_e[b], sh_oC[b * OUT_D + o], acc);
        atomicAdd(&g_wsum[o], acc);
    }

    // ---- phase 3: GRU, thread = (hidden dim d, cell-half) ----
    {
        const int d = lane128;
        ull r2[8], z2[8], n2[8], hn2[8];
        {
            ull br = pack2(g_gb[d]);
            ull bz = pack2(g_gb[HID_D + d]);
            ull bn = pack2(g_gb[2 * HID_D + d]);
            ull bh = pack2(g_gb[3 * HID_D + d]);
            #pragma unroll
            for (int q = 0; q < 8; q++) { r2[q] = br; z2[q] = bz; n2[q] = bn; hn2[q] = bh; }
        }
        #pragma unroll 4
        for (int k = 0; k < GIN; k++) {
            float2 wrz = g_WiRZ[k * HID_D + d];
            float  wn  = g_WiN[k * HID_D + d];
            ull wr2 = pack2(wrz.x), wz2 = pack2(wrz.y), wn2 = pack2(wn);
            const float* vp = sh_oT + k * SH + cb;
            #pragma unroll
            for (int q = 0; q < 4; q++) {
                ulonglong2 v = *(const ulonglong2*)(vp + q * 4);
                r2[2 * q]     = ffma2(wr2, v.x, r2[2 * q]);
                r2[2 * q + 1] = ffma2(wr2, v.y, r2[2 * q + 1]);
                z2[2 * q]     = ffma2(wz2, v.x, z2[2 * q]);
                z2[2 * q + 1] = ffma2(wz2, v.y, z2[2 * q + 1]);
                n2[2 * q]     = ffma2(wn2, v.x, n2[2 * q]);
                n2[2 * q + 1] = ffma2(wn2, v.y, n2[2 * q + 1]);
            }
        }
        #pragma unroll 4
        for (int k = 0; k < HID_D; k++) {
            float2 wrz = g_WhRZ[k * HID_D + d];
            float  wn  = g_WhN[k * HID_D + d];
            ull wr2 = pack2(wrz.x), wz2 = pack2(wrz.y), wn2 = pack2(wn);
            const float* vp = sh_h + k * SH + cb;
            #pragma unroll
            for (int q = 0; q < 4; q++) {
                ulonglong2 v = *(const ulonglong2*)(vp + q * 4);
                r2[2 * q]      = ffma2(wr2, v.x, r2[2 * q]);
                r2[2 * q + 1]  = ffma2(wr2, v.y, r2[2 * q + 1]);
                z2[2 * q]      = ffma2(wz2, v.x, z2[2 * q]);
                z2[2 * q + 1]  = ffma2(wz2, v.y, z2[2 * q + 1]);
                hn2[2 * q]     = ffma2(wn2, v.x, hn2[2 * q]);
                hn2[2 * q + 1] = ffma2(wn2, v.y, hn2[2 * q + 1]);
            }
        }
        // own-h re-read (coalesced, frees registers during GEMM loops)
        float h16[HALF];
        #pragma unroll
        for (int m = 0; m < HALF; m++)
            h16[m] = hiddens[(size_t)(n0 + cb + m) * HID_D + d];
        float fsum_local = 0.f;
        float* nout = newh_out + (size_t)(n0 + cb) * HID_D + d;
        #pragma unroll
        for (int q = 0; q < 8; q++) {
            float2 rf = unpk(r2[q]), zf = unpk(z2[q]);
            float2 inn = unpk(n2[q]), hnf = unpk(hn2[q]);
            {
                float r = 1.f / (1.f + expf(-rf.x));
                float z = 1.f / (1.f + expf(-zf.x));
                float nn = tanhf(inn.x + r * hnf.x);
                float nh = (1.f - z) * nn + z * h16[2 * q];
                fsum_local += nh;
                nout[(size_t)(2 * q) * HID_D] = nh;
            }
            {
                float r = 1.f / (1.f + expf(-rf.y));
                float z = 1.f / (1.f + expf(-zf.y));
                float nn = tanhf(inn.y + r * hnf.y);
                float nh = (1.f - z) * nn + z * h16[2 * q + 1];
                fsum_local += nh;
                nout[(size_t)(2 * q + 1) * HID_D] = nh;
            }
        }
        int f = blockIdx.x / (FS / CELLS);   // one faction per CTA
        atomicAdd(&g_fsum[f * HID_D + d], fsum_local);
    }
}

// ------------------------- faction means / global opinion -------------------
__global__ void faction_kernel() {
    int d = threadIdx.x;  // 128
    float s = 0.f;
    for (int f = 0; f < NF; f++) {
        float fm = g_fsum[f * HID_D + d] * (1.0f / FS);
        g_fm[f * HID_D + d] = fm;
        s += fm;
    }
    g_go[d] = s * (1.0f / NF);
}

// ------------------------- output head + t.mean ------------------------------
__global__ void head_kernel(const float* __restrict__ Wo, const float* __restrict__ bo,
                            float* __restrict__ out) {
    int i = threadIdx.x;  // 64
    float inv = 1.f / g_sumexp;
    float acc = bo[i];
    #pragma unroll 4
    for (int j = 0; j < OUT_D; j++)
        acc = fmaf(g_wsum[j] * inv, Wo[i * OUT_D + j], acc);
    out[i] = acc;
    if (i == 0) out[OUT_D] = g_tsum * (1.0f / N_CELLS);
}

// ------------------------- faction sync finalize (in place) ------------------
__global__ void __launch_bounds__(256) finalize_kernel(float* __restrict__ newh,
                                                       const int* __restrict__ step) {
    int idx = blockIdx.x * blockDim.x + threadIdx.x;  // < N_CELLS * HID_D
    int n = idx >> 7, d = idx & 127;
    float pre = newh[idx];
    int f = n >> 14;  // FS == 16384
    float v = 0.85f * pre + 0.15f * g_fm[f * HID_D + d];
    if (*step > 5 && (n & (FS - 1)) < DC)
        v = 0.85f * v + 0.15f * g_go[d];
    newh[idx] = v;
}

// ------------------------- launch ---------------------------------------------
extern "C" void kernel_launch(void* const* d_in, const int* in_sizes, int n_in,
                              void* d_out, int out_size) {
    const float* x       = (const float*)d_in[0];
    const float* hiddens = (const float*)d_in[1];
    const float* W1a = (const float*)d_in[2];  const float* b1a = (const float*)d_in[3];
    const float* W2a = (const float*)d_in[4];  const float* b2a = (const float*)d_in[5];
    const float* W1g = (const float*)d_in[6];  const float* b1g = (const float*)d_in[7];
    const float* W2g = (const float*)d_in[8];  const float* b2g = (const float*)d_in[9];
    const float* Wih = (const float*)d_in[10]; const float* Whh = (const float*)d_in[11];
    const float* bih = (const float*)d_in[12]; const float* bhh = (const float*)d_in[13];
    const float* Wo  = (const float*)d_in[14]; const float* bo  = (const float*)d_in[15];
    const int*   step = (const int*)d_in[16];

    float* out = (float*)d_out;
    float* newh = out + OUT_D + 1;  // [pred(64) | t.mean(1) | new_h(131072*128)]

    cudaFuncSetAttribute(main_kernel, cudaFuncAttributeMaxDynamicSharedMemorySize, SMEM_BYTES);

    prep_kernel<<<128, 256>>>(x, W1a, b1a, W1g, b1g, W2a, b2a, W2g, b2g,
                              Wih, Whh, bih, bhh);
    main_kernel<<<NCTAS, MT, SMEM_BYTES>>>(hiddens, newh);
    faction_kernel<<<1, HID_D>>>();
    head_kernel<<<1, OUT_D>>>(Wo, bo, out);
    finalize_kernel<<<(N_CELLS * HID_D) / 256, 256>>>(newh, step);
}